// round 1
// baseline (speedup 1.0000x reference)
#include <cuda_runtime.h>

// Shapes (fixed by the problem):
//  x1  [2,64,8,8,8,8]   x2 [2,32,16,16,16,16]
//  up_w[64,32,2,2,2,2]  up_b[32]
//  w1  [32,64,3,3,3,3]  b1[32]
//  w2  [32,32,3,3,3,3]  b2[32]
//  w3  [32,64]          b3[32]
//  out [2,32,16,16,16,16] fp32

// Scratch (static device globals — no allocation APIs allowed)
__device__ float g_x1u[2 * 32 * 65536];  // upsampled half of concat
__device__ float g_y1 [2 * 32 * 65536];  // relu(conv1) output

__device__ __forceinline__ unsigned long long pack2(float a, float b) {
    unsigned long long r;
    asm("mov.b64 %0, {%1, %2};" : "=l"(r) : "f"(a), "f"(b));
    return r;
}
__device__ __forceinline__ void unpack2(unsigned long long v, float &a, float &b) {
    asm("mov.b64 {%0, %1}, %2;" : "=f"(a), "=f"(b) : "l"(v));
}
// Packed dual FMA: d.lo += a.lo*b.lo ; d.hi += a.hi*b.hi  (FFMA2, sm_100+)
__device__ __forceinline__ void fma2(unsigned long long &d, unsigned long long a, unsigned long long b) {
    asm("fma.rn.f32x2 %0, %1, %2, %0;" : "+l"(d) : "l"(a), "l"(b));
}

// ---------------------------------------------------------------------------
// Transposed conv k=2 s=2: x1 [2,64,8^4] -> g_x1u [2,32,16^4]
// Block = (b,t,d,h) of the 8^4 input grid; thread = (co, w) : co=tid>>3, w=tid&7.
// Each thread produces the 16 (p,q,r,s) sub-positions for its (co, t,d,h,w).
// ---------------------------------------------------------------------------
__global__ __launch_bounds__(256) void upconv_kernel(
    const float* __restrict__ x1, const float* __restrict__ uw,
    const float* __restrict__ ub)
{
    int bx = blockIdx.x;
    int b = bx >> 9, t = (bx >> 6) & 7, d = (bx >> 3) & 7, h = bx & 7;
    int tid = threadIdx.x;
    int co = tid >> 3, w = tid & 7;

    float acc[16];
    float bias = ub[co];
#pragma unroll
    for (int a = 0; a < 16; a++) acc[a] = bias;

    const float* xp = x1 + (((size_t)b * 64) << 12) + (t << 9) + (d << 6) + (h << 3) + w;
    for (int ci = 0; ci < 64; ci++) {
        float xv = xp[(size_t)ci << 12];
        const float4* wp = (const float4*)(uw + (((size_t)ci * 32 + co) << 4));
#pragma unroll
        for (int q = 0; q < 4; q++) {
            float4 wv = wp[q];
            acc[q * 4 + 0] += xv * wv.x;
            acc[q * 4 + 1] += xv * wv.y;
            acc[q * 4 + 2] += xv * wv.z;
            acc[q * 4 + 3] += xv * wv.w;
        }
    }
    float* op = g_x1u + (((size_t)(b * 32 + co)) << 16);
#pragma unroll
    for (int a = 0; a < 16; a++) {
        int p = (a >> 3) & 1, q = (a >> 2) & 1, r = (a >> 1) & 1, s = a & 1;
        op[((2 * t + p) << 12) + ((2 * d + q) << 8) + ((2 * h + r) << 4) + (2 * w + s)] = acc[a];
    }
}

// ---------------------------------------------------------------------------
// 4D conv, kernel 3^4, pad 1, Cout=32. One block per (b,t,d); 256 threads =
// one (h,w) each; 32 Cout accumulators packed as 16 f32x2 registers.
// Input channels come from two 32-channel halves (concat without materializing):
//   CIN==64: c<32 -> src0 (x2), c>=32 -> src1 (g_x1u).  CIN==32: src0 only.
// SKIP: fused 1x1 conv (w3,b3) over the 64-channel concat + final relu.
// ---------------------------------------------------------------------------
template <int CIN, bool RELU, bool SKIP>
__global__ __launch_bounds__(256, 2) void conv_kernel(
    const float* __restrict__ src0, const float* __restrict__ src1,
    const float* __restrict__ wgt,  const float* __restrict__ bias,
    const float* __restrict__ sk0,  const float* __restrict__ sk1,
    const float* __restrict__ w3,   const float* __restrict__ b3,
    float* __restrict__ out)
{
    constexpr int CI  = 16;          // ci chunk per stage
    constexpr int NCH = CIN / CI;

    __shared__ __align__(16) float Xs[CI * 18 * 18];   // haloed (h,w) plane per ci
    __shared__ __align__(16) float Ws[CI * 9 * 32];    // [ci][kh][kw][co]

    int b = blockIdx.y;
    int t = blockIdx.x >> 4, d = blockIdx.x & 15;
    int tid = threadIdx.x;
    int h = tid >> 4, w = tid & 15;

    unsigned long long acc2[16];
#pragma unroll
    for (int j = 0; j < 16; j++) {
        float v0 = bias[2 * j], v1 = bias[2 * j + 1];
        if constexpr (SKIP) { v0 += b3[2 * j]; v1 += b3[2 * j + 1]; }
        acc2[j] = pack2(v0, v1);
    }

    for (int kt = 0; kt < 3; kt++) {
        int tt = t + kt - 1;
        if (tt < 0 || tt >= 16) continue;
        for (int kd = 0; kd < 3; kd++) {
            int dd = d + kd - 1;
            if (dd < 0 || dd >= 16) continue;
            for (int ch = 0; ch < NCH; ch++) {
                __syncthreads();
                // Stage input plane (18x18 halo, zero padded) for CI channels
                for (int idx = tid; idx < CI * 324; idx += 256) {
                    int ci = idx / 324;
                    int rr = idx - ci * 324;
                    int r = rr / 18, c2 = rr - r * 18;
                    int hh = r - 1, ww = c2 - 1;
                    float v = 0.f;
                    if ((unsigned)hh < 16u && (unsigned)ww < 16u) {
                        int c = ch * CI + ci;
                        const float* sp = (CIN == 64 && c >= 32)
                            ? (src1 + (((size_t)(b * 32 + (c - 32))) << 16))
                            : (src0 + (((size_t)(b * 32 + (c & 31))) << 16));
                        v = sp[(tt << 12) + (dd << 8) + (hh << 4) + ww];
                    }
                    Xs[idx] = v;
                }
                // Stage weights for this (kt,kd) tap, reordered co-innermost
                for (int idx = tid; idx < CI * 9 * 32; idx += 256) {
                    int co = idx & 31;
                    int r = idx >> 5;
                    int kw = r % 3;
                    int kh = (r / 3) % 3;
                    int ci = r / 9;
                    int c = ch * CI + ci;
                    Ws[idx] = wgt[((size_t)co * CIN + c) * 81 + kt * 27 + kd * 9 + kh * 3 + kw];
                }
                __syncthreads();

                for (int ci = 0; ci < CI; ci++) {
                    const float* xb = Xs + ci * 324 + h * 18 + w;
                    const float* wb = Ws + ci * 9 * 32;
#pragma unroll
                    for (int kh = 0; kh < 3; kh++) {
#pragma unroll
                        for (int kw = 0; kw < 3; kw++) {
                            float xv = xb[kh * 18 + kw];
                            unsigned long long xx = pack2(xv, xv);
                            const ulonglong2* wp = (const ulonglong2*)(wb + (kh * 3 + kw) * 32);
#pragma unroll
                            for (int q = 0; q < 8; q++) {
                                ulonglong2 wv = wp[q];
                                fma2(acc2[2 * q],     xx, wv.x);
                                fma2(acc2[2 * q + 1], xx, wv.y);
                            }
                        }
                    }
                }
            }
        }
    }

    if constexpr (SKIP) {
        // Fused 1x1 conv over the 64-channel concat at the center position
        int pos = (h << 4) + w;
        for (int ch = 0; ch < 4; ch++) {
            __syncthreads();
            for (int idx = tid; idx < 16 * 256; idx += 256) {
                int ci = idx >> 8, p = idx & 255;
                int c = ch * 16 + ci;
                const float* sp = (c < 32)
                    ? (sk0 + (((size_t)(b * 32 + c)) << 16))
                    : (sk1 + (((size_t)(b * 32 + c - 32)) << 16));
                Xs[idx] = sp[(t << 12) + (d << 8) + p];
            }
            for (int idx = tid; idx < 512; idx += 256) {
                int ci = idx >> 5, co = idx & 31;
                Ws[idx] = w3[co * 64 + ch * 16 + ci];
            }
            __syncthreads();
            for (int ci = 0; ci < 16; ci++) {
                float xv = Xs[(ci << 8) + pos];
                unsigned long long xx = pack2(xv, xv);
                const ulonglong2* wp = (const ulonglong2*)(Ws + (ci << 5));
#pragma unroll
                for (int q = 0; q < 8; q++) {
                    ulonglong2 wv = wp[q];
                    fma2(acc2[2 * q],     xx, wv.x);
                    fma2(acc2[2 * q + 1], xx, wv.y);
                }
            }
        }
    }

    size_t obase = ((size_t)b * 32) << 16;
    int pos = (t << 12) + (d << 8) + (h << 4) + w;
#pragma unroll
    for (int j = 0; j < 16; j++) {
        float v0, v1;
        unpack2(acc2[j], v0, v1);
        if (RELU) { v0 = fmaxf(v0, 0.f); v1 = fmaxf(v1, 0.f); }
        out[obase + (((size_t)(2 * j)) << 16) + pos]     = v0;
        out[obase + (((size_t)(2 * j + 1)) << 16) + pos] = v1;
    }
}

extern "C" void kernel_launch(void* const* d_in, const int* in_sizes, int n_in,
                              void* d_out, int out_size)
{
    const float* x1   = (const float*)d_in[0];
    const float* x2   = (const float*)d_in[1];
    const float* up_w = (const float*)d_in[2];
    const float* up_b = (const float*)d_in[3];
    const float* w1   = (const float*)d_in[4];
    const float* b1   = (const float*)d_in[5];
    const float* w2   = (const float*)d_in[6];
    const float* b2   = (const float*)d_in[7];
    const float* w3   = (const float*)d_in[8];
    const float* b3   = (const float*)d_in[9];
    float* out = (float*)d_out;

    float *px1u = nullptr, *py1 = nullptr;
    cudaGetSymbolAddress((void**)&px1u, g_x1u);
    cudaGetSymbolAddress((void**)&py1,  g_y1);

    // 1) upsample x1 -> g_x1u (the second half of the channel concat)
    upconv_kernel<<<1024, 256>>>(x1, up_w, up_b);

    // 2) Y1 = relu(conv4d(concat, w1, b1, pad=1)) -> g_y1
    conv_kernel<64, true, false><<<dim3(256, 2), 256>>>(
        x2, px1u, w1, b1, nullptr, nullptr, nullptr, nullptr, py1);

    // 3) out = relu(conv4d(Y1, w2, b2, pad=1) + conv1x1(concat, w3, b3))
    conv_kernel<32, true, true><<<dim3(256, 2), 256>>>(
        py1, nullptr, w2, b2, x2, px1u, w3, b3, out);
}

// round 2
// speedup vs baseline: 1.2830x; 1.2830x over previous
#include <cuda_runtime.h>

// Shapes (fixed):
//  x1  [2,64,8,8,8,8]   x2 [2,32,16,16,16,16]
//  up_w[64,32,2,2,2,2]  up_b[32]
//  w1  [32,64,3,3,3,3]  b1[32]
//  w2  [32,32,3,3,3,3]  b2[32]
//  w3  [32,64]          b3[32]
//  out [2,32,16,16,16,16] fp32

__device__ float g_x1u[2 * 32 * 65536];  // upsampled half of concat
__device__ float g_y1 [2 * 32 * 65536];  // relu(conv1) output

__device__ __forceinline__ unsigned long long pack2(float a, float b) {
    unsigned long long r;
    asm("mov.b64 %0, {%1, %2};" : "=l"(r) : "f"(a), "f"(b));
    return r;
}
__device__ __forceinline__ void unpack2(unsigned long long v, float &a, float &b) {
    asm("mov.b64 {%0, %1}, %2;" : "=f"(a), "=f"(b) : "l"(v));
}
// Packed dual FMA: d.lo += a.lo*b.lo ; d.hi += a.hi*b.hi  (sm_100+)
__device__ __forceinline__ void fma2(unsigned long long &d, unsigned long long a, unsigned long long b) {
    asm("fma.rn.f32x2 %0, %1, %2, %0;" : "+l"(d) : "l"(a), "l"(b));
}

// ---------------------------------------------------------------------------
// Transposed conv k=2 s=2: x1 [2,64,8^4] -> g_x1u [2,32,16^4]
// ---------------------------------------------------------------------------
__global__ __launch_bounds__(256) void upconv_kernel(
    const float* __restrict__ x1, const float* __restrict__ uw,
    const float* __restrict__ ub)
{
    int bx = blockIdx.x;
    int b = bx >> 9, t = (bx >> 6) & 7, d = (bx >> 3) & 7, h = bx & 7;
    int tid = threadIdx.x;
    int co = tid >> 3, w = tid & 7;

    float acc[16];
    float bias = ub[co];
#pragma unroll
    for (int a = 0; a < 16; a++) acc[a] = bias;

    const float* xp = x1 + (((size_t)b * 64) << 12) + (t << 9) + (d << 6) + (h << 3) + w;
    for (int ci = 0; ci < 64; ci++) {
        float xv = xp[(size_t)ci << 12];
        const float4* wp = (const float4*)(uw + (((size_t)ci * 32 + co) << 4));
#pragma unroll
        for (int q = 0; q < 4; q++) {
            float4 wv = wp[q];
            acc[q * 4 + 0] += xv * wv.x;
            acc[q * 4 + 1] += xv * wv.y;
            acc[q * 4 + 2] += xv * wv.z;
            acc[q * 4 + 3] += xv * wv.w;
        }
    }
    float* op = g_x1u + (((size_t)(b * 32 + co)) << 16);
#pragma unroll
    for (int a = 0; a < 16; a++) {
        int p = (a >> 3) & 1, q = (a >> 2) & 1, r = (a >> 1) & 1, s = a & 1;
        op[((2 * t + p) << 12) + ((2 * d + q) << 8) + ((2 * h + r) << 4) + (2 * w + s)] = acc[a];
    }
}

// ---------------------------------------------------------------------------
// 4D conv, kernel 3^4, pad 1, Cout=32. One block per (b,t,d); 128 threads,
// each handling TWO (h,w) positions: (h,w) and (h+8,w). The two positions
// share the staged input plane AND the weight registers, so per (ci,kh,kw):
//   2 x-LDS + 8 w-LDS.128 + 32 FFMA2  (FMA-pipe-bound, 2 indep acc chains)
// Channels come from two 32-ch halves (concat never materialized).
// SKIP: fused 1x1 conv (w3,b3) over the 64-ch concat + final relu.
// ---------------------------------------------------------------------------
template <int CIN, bool RELU, bool SKIP>
__global__ __launch_bounds__(128, 4) void conv_kernel(
    const float* __restrict__ src0, const float* __restrict__ src1,
    const float* __restrict__ wgt,  const float* __restrict__ bias,
    const float* __restrict__ sk0,  const float* __restrict__ sk1,
    const float* __restrict__ w3,   const float* __restrict__ b3,
    float* __restrict__ out)
{
    constexpr int CI  = 16;          // ci chunk per stage
    constexpr int NCH = CIN / CI;

    __shared__ __align__(16) float Xs[CI * 18 * 18];   // haloed (h,w) plane per ci
    __shared__ __align__(16) float Ws[CI * 9 * 32];    // [ci][kh][kw][co]

    int b = blockIdx.y;
    int t = blockIdx.x >> 4, d = blockIdx.x & 15;
    int tid = threadIdx.x;
    int h = tid >> 4;        // 0..7  (second position is h+8)
    int w = tid & 15;

    unsigned long long accA[16], accB[16];
#pragma unroll
    for (int j = 0; j < 16; j++) {
        float v0 = bias[2 * j], v1 = bias[2 * j + 1];
        if constexpr (SKIP) { v0 += b3[2 * j]; v1 += b3[2 * j + 1]; }
        accA[j] = pack2(v0, v1);
        accB[j] = accA[j];
    }

    for (int kt = 0; kt < 3; kt++) {
        int tt = t + kt - 1;
        if (tt < 0 || tt >= 16) continue;
        for (int kd = 0; kd < 3; kd++) {
            int dd = d + kd - 1;
            if (dd < 0 || dd >= 16) continue;
#pragma unroll 1
            for (int ch = 0; ch < NCH; ch++) {
                __syncthreads();
                // Stage input plane (18x18 halo, zero padded) for CI channels
                for (int idx = tid; idx < CI * 324; idx += 128) {
                    int ci = idx / 324;
                    int rr = idx - ci * 324;
                    int r = rr / 18, c2 = rr - r * 18;
                    int hh = r - 1, ww = c2 - 1;
                    float v = 0.f;
                    if ((unsigned)hh < 16u && (unsigned)ww < 16u) {
                        int c = ch * CI + ci;
                        const float* sp = (CIN == 64 && c >= 32)
                            ? (src1 + (((size_t)(b * 32 + (c - 32))) << 16))
                            : (src0 + (((size_t)(b * 32 + (c & 31))) << 16));
                        v = sp[(tt << 12) + (dd << 8) + (hh << 4) + ww];
                    }
                    Xs[idx] = v;
                }
                // Stage weights for this (kt,kd) tap, co-innermost
                for (int idx = tid; idx < CI * 9 * 32; idx += 128) {
                    int co = idx & 31;
                    int r = idx >> 5;
                    int kw = r % 3;
                    int kh = (r / 3) % 3;
                    int ci = r / 9;
                    int c = ch * CI + ci;
                    Ws[idx] = wgt[((size_t)co * CIN + c) * 81 + kt * 27 + kd * 9 + kh * 3 + kw];
                }
                __syncthreads();

#pragma unroll 1
                for (int ci = 0; ci < CI; ci++) {
                    const float* xb = Xs + ci * 324 + h * 18 + w;
                    const float* wb = Ws + ci * 9 * 32;
#pragma unroll
                    for (int kh = 0; kh < 3; kh++) {
#pragma unroll
                        for (int kw = 0; kw < 3; kw++) {
                            float xv0 = xb[kh * 18 + kw];
                            float xv1 = xb[kh * 18 + kw + 144];   // (h+8) row
                            unsigned long long xx0 = pack2(xv0, xv0);
                            unsigned long long xx1 = pack2(xv1, xv1);
                            const ulonglong2* wp = (const ulonglong2*)(wb + (kh * 3 + kw) * 32);
#pragma unroll
                            for (int q = 0; q < 8; q++) {
                                ulonglong2 wv = wp[q];
                                fma2(accA[2 * q],     xx0, wv.x);
                                fma2(accA[2 * q + 1], xx0, wv.y);
                                fma2(accB[2 * q],     xx1, wv.x);
                                fma2(accB[2 * q + 1], xx1, wv.y);
                            }
                        }
                    }
                }
            }
        }
    }

    int pos = (h << 4) + w;      // second position = pos + 128

    if constexpr (SKIP) {
        // Fused 1x1 conv over the 64-channel concat
#pragma unroll 1
        for (int ch = 0; ch < 4; ch++) {
            __syncthreads();
            for (int idx = tid; idx < 16 * 256; idx += 128) {
                int ci = idx >> 8, p = idx & 255;
                int c = ch * 16 + ci;
                const float* sp = (c < 32)
                    ? (sk0 + (((size_t)(b * 32 + c)) << 16))
                    : (sk1 + (((size_t)(b * 32 + c - 32)) << 16));
                Xs[idx] = sp[(t << 12) + (d << 8) + p];
            }
            for (int idx = tid; idx < 512; idx += 128) {
                int ci = idx >> 5, co = idx & 31;
                Ws[idx] = w3[co * 64 + ch * 16 + ci];
            }
            __syncthreads();
#pragma unroll 1
            for (int ci = 0; ci < 16; ci++) {
                float xv0 = Xs[(ci << 8) + pos];
                float xv1 = Xs[(ci << 8) + pos + 128];
                unsigned long long xx0 = pack2(xv0, xv0);
                unsigned long long xx1 = pack2(xv1, xv1);
                const ulonglong2* wp = (const ulonglong2*)(Ws + (ci << 5));
#pragma unroll
                for (int q = 0; q < 8; q++) {
                    ulonglong2 wv = wp[q];
                    fma2(accA[2 * q],     xx0, wv.x);
                    fma2(accA[2 * q + 1], xx0, wv.y);
                    fma2(accB[2 * q],     xx1, wv.x);
                    fma2(accB[2 * q + 1], xx1, wv.y);
                }
            }
        }
    }

    size_t obase = ((size_t)b * 32) << 16;
    int opos = (t << 12) + (d << 8) + pos;
#pragma unroll
    for (int j = 0; j < 16; j++) {
        float a0, a1, c0, c1;
        unpack2(accA[j], a0, a1);
        unpack2(accB[j], c0, c1);
        if (RELU) {
            a0 = fmaxf(a0, 0.f); a1 = fmaxf(a1, 0.f);
            c0 = fmaxf(c0, 0.f); c1 = fmaxf(c1, 0.f);
        }
        size_t o0 = obase + (((size_t)(2 * j)) << 16) + opos;
        size_t o1 = obase + (((size_t)(2 * j + 1)) << 16) + opos;
        out[o0]       = a0;
        out[o1]       = a1;
        out[o0 + 128] = c0;   // (h+8) position
        out[o1 + 128] = c1;
    }
}

extern "C" void kernel_launch(void* const* d_in, const int* in_sizes, int n_in,
                              void* d_out, int out_size)
{
    const float* x1   = (const float*)d_in[0];
    const float* x2   = (const float*)d_in[1];
    const float* up_w = (const float*)d_in[2];
    const float* up_b = (const float*)d_in[3];
    const float* w1   = (const float*)d_in[4];
    const float* b1   = (const float*)d_in[5];
    const float* w2   = (const float*)d_in[6];
    const float* b2   = (const float*)d_in[7];
    const float* w3   = (const float*)d_in[8];
    const float* b3   = (const float*)d_in[9];
    float* out = (float*)d_out;

    float *px1u = nullptr, *py1 = nullptr;
    cudaGetSymbolAddress((void**)&px1u, g_x1u);
    cudaGetSymbolAddress((void**)&py1,  g_y1);

    // 1) upsample x1 -> g_x1u (second half of channel concat)
    upconv_kernel<<<1024, 256>>>(x1, up_w, up_b);

    // 2) Y1 = relu(conv4d(concat, w1, b1, pad=1)) -> g_y1
    conv_kernel<64, true, false><<<dim3(256, 2), 128>>>(
        x2, px1u, w1, b1, nullptr, nullptr, nullptr, nullptr, py1);

    // 3) out = relu(conv4d(Y1, w2, b2, pad=1) + conv1x1(concat, w3, b3))
    conv_kernel<32, true, true><<<dim3(256, 2), 128>>>(
        py1, nullptr, w2, b2, x2, px1u, w3, b3, out);
}